// round 1
// baseline (speedup 1.0000x reference)
#include <cuda_runtime.h>
#include <math.h>

#define NNODES 50000
#define NEDGES 800000

// ---------------- scratch (static device globals; no allocation) ----------------
__device__ __align__(16) float g_x  [NNODES * 128];  // Tx0 of conv1
__device__ __align__(16) float g_t1 [NNODES * 128];  // Tx1 buffer
__device__ __align__(16) float g_p  [NNODES * 128];  // prop(Tx1) buffer
__device__ __align__(16) float g_h1 [NNODES * 128];  // conv1 output
__device__ __align__(16) float g_tmp[NNODES * 128];  // elu intermediate
__device__ __align__(16) float g_dinv[NNODES];       // degree -> d^{-1/2}

// ---------------- small kernels ----------------
__global__ void zero_kernel(float4* __restrict__ p, int n4) {
    int i = blockIdx.x * blockDim.x + threadIdx.x;
    if (i < n4) p[i] = make_float4(0.f, 0.f, 0.f, 0.f);
}

__global__ void degree_kernel(const int* __restrict__ src, float* __restrict__ deg, int E) {
    int e = blockIdx.x * blockDim.x + threadIdx.x;
    if (e < E) atomicAdd(&deg[src[e]], 1.0f);
}

__global__ void dinv_kernel(float* __restrict__ deg, int n) {
    int i = blockIdx.x * blockDim.x + threadIdx.x;
    if (i < n) {
        float d = deg[i];
        deg[i] = (d > 0.f) ? rsqrtf(d) : 0.f;
    }
}

// x = concat(emb_id[a1], emb_len[a0], emb_lng[a2], emb_lat[a3], vis)  -> [N,128]
__global__ void build_x_kernel(const int* __restrict__ node_attr,
                               const float* __restrict__ vis,
                               const float* __restrict__ emb_len,
                               const float* __restrict__ emb_id,
                               const float* __restrict__ emb_lng,
                               const float* __restrict__ emb_lat,
                               float* __restrict__ x, int n) {
    int idx = blockIdx.x * blockDim.x + threadIdx.x;
    if (idx >= n * 128) return;
    int node = idx >> 7;
    int f = idx & 127;
    float v;
    if (f < 16) {
        int a = node_attr[node * 4 + 1];
        v = emb_id[a * 16 + f];
    } else if (f < 32) {
        int a = node_attr[node * 4 + 0];
        v = emb_len[a * 16 + (f - 16)];
    } else if (f < 48) {
        int a = node_attr[node * 4 + 2];
        v = emb_lng[a * 16 + (f - 32)];
    } else if (f < 64) {
        int a = node_attr[node * 4 + 3];
        v = emb_lat[a * 16 + (f - 48)];
    } else {
        v = vis[node * 64 + (f - 64)];
    }
    x[idx] = v;
}

// out[dst] += (-dinv[src]*dinv[dst]) * t[src]  — one warp per edge, vector red.
__global__ void prop_kernel(const float* __restrict__ t,
                            const int* __restrict__ src,
                            const int* __restrict__ dst,
                            const float* __restrict__ dinv,
                            float* __restrict__ out, int E) {
    int tid = blockIdx.x * blockDim.x + threadIdx.x;
    int e = tid >> 5;
    int lane = tid & 31;
    if (e >= E) return;
    int s = src[e];
    int d = dst[e];
    float w = -dinv[s] * dinv[d];
    float4 v = *(const float4*)(t + (size_t)s * 128 + lane * 4);
    float rx = v.x * w, ry = v.y * w, rz = v.z * w, rw = v.w * w;
    float* p = out + (size_t)d * 128 + lane * 4;
    asm volatile("red.global.add.v4.f32 [%0], {%1,%2,%3,%4};"
                 :: "l"(p), "f"(rx), "f"(ry), "f"(rz), "f"(rw) : "memory");
}

// ---------------- GEMM ----------------
// C[M,NOUT] = A[M,KTOT] @ W[KTOT,NOUT] + bias ; epilogue EPI: 0=none 1=relu 2=elu
// CHEB: A columns 0..127 = A0, 128..255 = A1, 256..383 = 2*A2 - A0
template<int KTOT, int NOUT, int EPI, bool CHEB>
__global__ void __launch_bounds__((NOUT / 8) * 16)
gemm_kernel(const float* __restrict__ A0,
            const float* __restrict__ A1,
            const float* __restrict__ A2,
            const float* __restrict__ W,
            const float* __restrict__ bias,
            float* __restrict__ C, int M) {
    constexpr int BM = 128, BK = 16, BN = NOUT;
    constexpr int TX = BN / 8, TY = BM / 8, NT = TX * TY;
    __shared__ float As[BK][BM + 4];
    __shared__ float Bs[BK][BN + 4];

    const int tid = threadIdx.x;
    const int tx = tid % TX, ty = tid / TX;
    const int row0 = blockIdx.x * BM;

    float acc[8][8];
#pragma unroll
    for (int i = 0; i < 8; i++)
#pragma unroll
        for (int j = 0; j < 8; j++) acc[i][j] = 0.f;

    for (int k0 = 0; k0 < KTOT; k0 += BK) {
        // A tile: BM x BK, stored transposed in As[k][m]
        constexpr int NA4 = BM * BK / 4;  // 512 float4s
#pragma unroll
        for (int it = 0; it < NA4 / NT; it++) {
            int i = tid + it * NT;
            int r = i >> 2;            // row within tile (BK/4 == 4)
            int c4 = i & 3;            // which float4 along K
            int grow = row0 + r;
            int gk = k0 + c4 * 4;
            float4 v = make_float4(0.f, 0.f, 0.f, 0.f);
            if (grow < M) {
                if (CHEB) {
                    if (gk < 128) {
                        v = *(const float4*)(A0 + (size_t)grow * 128 + gk);
                    } else if (gk < 256) {
                        v = *(const float4*)(A1 + (size_t)grow * 128 + (gk - 128));
                    } else {
                        float4 p = *(const float4*)(A2 + (size_t)grow * 128 + (gk - 256));
                        float4 t = *(const float4*)(A0 + (size_t)grow * 128 + (gk - 256));
                        v = make_float4(2.f * p.x - t.x, 2.f * p.y - t.y,
                                        2.f * p.z - t.z, 2.f * p.w - t.w);
                    }
                } else {
                    v = *(const float4*)(A0 + (size_t)grow * KTOT + gk);
                }
            }
            int kk = c4 * 4;
            As[kk + 0][r] = v.x;
            As[kk + 1][r] = v.y;
            As[kk + 2][r] = v.z;
            As[kk + 3][r] = v.w;
        }
        // B tile: BK x BN
        constexpr int NB4 = BK * BN / 4;
#pragma unroll
        for (int it = 0; it < NB4 / NT; it++) {
            int i = tid + it * NT;
            int kk = i / (BN / 4);
            int c = (i % (BN / 4)) * 4;
            *(float4*)&Bs[kk][c] = *(const float4*)(W + (size_t)(k0 + kk) * NOUT + c);
        }
        __syncthreads();

#pragma unroll
        for (int k = 0; k < BK; k++) {
            float4 a0 = *(const float4*)&As[k][ty * 8];
            float4 a1 = *(const float4*)&As[k][ty * 8 + 4];
            float4 b0 = *(const float4*)&Bs[k][tx * 8];
            float4 b1 = *(const float4*)&Bs[k][tx * 8 + 4];
            float a[8] = {a0.x, a0.y, a0.z, a0.w, a1.x, a1.y, a1.z, a1.w};
            float b[8] = {b0.x, b0.y, b0.z, b0.w, b1.x, b1.y, b1.z, b1.w};
#pragma unroll
            for (int i = 0; i < 8; i++)
#pragma unroll
                for (int j = 0; j < 8; j++) acc[i][j] += a[i] * b[j];
        }
        __syncthreads();
    }

    // epilogue
#pragma unroll
    for (int i = 0; i < 8; i++) {
        int grow = row0 + ty * 8 + i;
        if (grow >= M) continue;
#pragma unroll
        for (int j = 0; j < 8; j++) {
            int col = tx * 8 + j;
            float v = acc[i][j] + bias[col];
            if (EPI == 1) v = fmaxf(v, 0.f);
            else if (EPI == 2) v = (v > 0.f) ? v : expm1f(v);
            C[(size_t)grow * NOUT + col] = v;
        }
    }
}

// ---------------- launch ----------------
extern "C" void kernel_launch(void* const* d_in, const int* in_sizes, int n_in,
                              void* d_out, int out_size) {
    const int* edge_index = (const int*)d_in[0];
    const int* node_attr = (const int*)d_in[1];
    const float* vis     = (const float*)d_in[2];
    const float* emb_len = (const float*)d_in[3];
    const float* emb_id  = (const float*)d_in[4];
    const float* emb_lng = (const float*)d_in[5];
    const float* emb_lat = (const float*)d_in[6];
    const float* W0  = (const float*)d_in[7];
    const float* b0  = (const float*)d_in[8];
    const float* W1  = (const float*)d_in[9];
    const float* b1  = (const float*)d_in[10];
    const float* P1  = (const float*)d_in[11];
    const float* pb1 = (const float*)d_in[12];
    const float* P2  = (const float*)d_in[13];
    const float* pb2 = (const float*)d_in[14];

    const int E = in_sizes[0] / 2;
    const int N = in_sizes[1] / 4;
    const int* src = edge_index;
    const int* dst = edge_index + E;

    float *x, *t1, *p, *h1, *tmp, *dinv;
    cudaGetSymbolAddress((void**)&x,    g_x);
    cudaGetSymbolAddress((void**)&t1,   g_t1);
    cudaGetSymbolAddress((void**)&p,    g_p);
    cudaGetSymbolAddress((void**)&h1,   g_h1);
    cudaGetSymbolAddress((void**)&tmp,  g_tmp);
    cudaGetSymbolAddress((void**)&dinv, g_dinv);

    float* hout = (float*)d_out;                 // [N,128]
    float* zout = hout + (size_t)N * 128;        // [N,64]

    const int n4_node = (N * 128) / 4;           // float4 count of a [N,128] buffer
    const int ZB = 256;
    const int prop_threads = E * 32;
    const int prop_blocks = (prop_threads + 255) / 256;
    const int gemm_blocks = (N + 127) / 128;

    // degree -> dinv
    zero_kernel<<<(N / 4 + ZB - 1) / ZB, ZB>>>((float4*)dinv, N / 4);
    degree_kernel<<<(E + 255) / 256, 256>>>(src, dinv, E);
    dinv_kernel<<<(N + 255) / 256, 256>>>(dinv, N);

    // feature assembly
    build_x_kernel<<<(N * 128 + 255) / 256, 256>>>(node_attr, vis, emb_len, emb_id,
                                                   emb_lng, emb_lat, x, N);

    // ---- conv1 ----
    zero_kernel<<<(n4_node + ZB - 1) / ZB, ZB>>>((float4*)t1, n4_node);
    prop_kernel<<<prop_blocks, 256>>>(x, src, dst, dinv, t1, E);
    zero_kernel<<<(n4_node + ZB - 1) / ZB, ZB>>>((float4*)p, n4_node);
    prop_kernel<<<prop_blocks, 256>>>(t1, src, dst, dinv, p, E);
    gemm_kernel<384, 128, 1, true><<<gemm_blocks, 256>>>(x, t1, p, W0, b0, h1, N);

    // ---- conv2 ----
    zero_kernel<<<(n4_node + ZB - 1) / ZB, ZB>>>((float4*)t1, n4_node);
    prop_kernel<<<prop_blocks, 256>>>(h1, src, dst, dinv, t1, E);
    zero_kernel<<<(n4_node + ZB - 1) / ZB, ZB>>>((float4*)p, n4_node);
    prop_kernel<<<prop_blocks, 256>>>(t1, src, dst, dinv, p, E);
    gemm_kernel<384, 128, 1, true><<<gemm_blocks, 256>>>(h1, t1, p, W1, b1, hout, N);

    // ---- projection head ----
    gemm_kernel<128, 128, 2, false><<<gemm_blocks, 256>>>(hout, nullptr, nullptr, P1, pb1, tmp, N);
    gemm_kernel<128, 64, 0, false><<<gemm_blocks, 128>>>(tmp, nullptr, nullptr, P2, pb2, zout, N);
}

// round 2
// speedup vs baseline: 1.7630x; 1.7630x over previous
#include <cuda_runtime.h>
#include <math.h>

#define NNODES 50000
#define NEDGES 800000

// ---------------- scratch (static device globals; no allocation) ----------------
__device__ __align__(16) float g_x  [NNODES * 128];
__device__ __align__(16) float g_t1 [NNODES * 128];
__device__ __align__(16) float g_p  [NNODES * 128];
__device__ __align__(16) float g_h1 [NNODES * 128];
__device__ __align__(16) float g_tmp[NNODES * 128];
__device__ float g_dinv[NNODES];
__device__ int   g_deg [NNODES];     // out-degree (by src)
__device__ int   g_cnt [NNODES];     // in-count (by dst)
__device__ int   g_rs  [NNODES];     // CSR row_start (by dst)
__device__ int   g_rf  [NNODES];     // fill cursor
__device__ int   g_bsum[256];
__device__ int   g_boff[256];
__device__ int   g_esrc[NEDGES];     // CSR src per slot
__device__ float g_ew  [NEDGES];     // CSR weight per slot

// ---------------- small kernels ----------------
__global__ void zero_int_kernel(int* __restrict__ a, int* __restrict__ b, int n) {
    int i = blockIdx.x * blockDim.x + threadIdx.x;
    if (i < n) { a[i] = 0; b[i] = 0; }
}

__global__ void count_kernel(const int* __restrict__ src, const int* __restrict__ dst,
                             int* __restrict__ deg, int* __restrict__ cnt, int E) {
    int e = blockIdx.x * blockDim.x + threadIdx.x;
    if (e < E) {
        atomicAdd(&deg[src[e]], 1);
        atomicAdd(&cnt[dst[e]], 1);
    }
}

__global__ void dinv_kernel(const int* __restrict__ deg, float* __restrict__ dinv, int n) {
    int i = blockIdx.x * blockDim.x + threadIdx.x;
    if (i < n) {
        int d = deg[i];
        dinv[i] = (d > 0) ? rsqrtf((float)d) : 0.f;
    }
}

// ---------------- scan (exclusive prefix over cnt -> row_start) ----------------
__device__ __forceinline__ int block_incl_scan(int v, int* wsum) {
    int lane = threadIdx.x & 31, wid = threadIdx.x >> 5;
    int x = v;
#pragma unroll
    for (int o = 1; o < 32; o <<= 1) {
        int y = __shfl_up_sync(0xffffffffu, x, o);
        if (lane >= o) x += y;
    }
    if (lane == 31) wsum[wid] = x;
    __syncthreads();
    if (wid == 0) {
        int s = (lane < 8) ? wsum[lane] : 0;
#pragma unroll
        for (int o = 1; o < 8; o <<= 1) {
            int y = __shfl_up_sync(0xffffffffu, s, o);
            if (lane >= o) s += y;
        }
        if (lane < 8) wsum[lane] = s;
    }
    __syncthreads();
    int off = (wid > 0) ? wsum[wid - 1] : 0;
    return x + off;
}

__global__ void scan_block_sum(const int* __restrict__ cnt, int* __restrict__ bsum, int n) {
    __shared__ int wsum[8];
    int i = blockIdx.x * 256 + threadIdx.x;
    int v = (i < n) ? cnt[i] : 0;
    int lane = threadIdx.x & 31, wid = threadIdx.x >> 5;
#pragma unroll
    for (int o = 16; o > 0; o >>= 1) v += __shfl_down_sync(0xffffffffu, v, o);
    if (lane == 0) wsum[wid] = v;
    __syncthreads();
    if (threadIdx.x == 0) {
        int s = 0;
#pragma unroll
        for (int k = 0; k < 8; k++) s += wsum[k];
        bsum[blockIdx.x] = s;
    }
}

__global__ void scan_top(const int* __restrict__ bsum, int* __restrict__ boff, int nb) {
    __shared__ int wsum[8];
    int t = threadIdx.x;
    int v = (t < nb) ? bsum[t] : 0;
    int incl = block_incl_scan(v, wsum);
    if (t < nb) boff[t] = incl - v;
}

__global__ void scan_final(const int* __restrict__ cnt, const int* __restrict__ boff,
                           int* __restrict__ rs, int* __restrict__ rf, int n) {
    __shared__ int wsum[8];
    int i = blockIdx.x * 256 + threadIdx.x;
    int v = (i < n) ? cnt[i] : 0;
    int incl = block_incl_scan(v, wsum);
    int excl = incl - v + boff[blockIdx.x];
    if (i < n) { rs[i] = excl; rf[i] = excl; }
}

__global__ void fill_kernel(const int* __restrict__ src, const int* __restrict__ dst,
                            const float* __restrict__ dinv,
                            int* __restrict__ rf, int* __restrict__ esrc,
                            float* __restrict__ ew, int E) {
    int e = blockIdx.x * blockDim.x + threadIdx.x;
    if (e < E) {
        int s = src[e], d = dst[e];
        int pos = atomicAdd(&rf[d], 1);
        esrc[pos] = s;
        ew[pos] = -dinv[s] * dinv[d];
    }
}

// ---------------- feature assembly (float4) ----------------
__global__ void build_x_kernel(const int* __restrict__ node_attr,
                               const float4* __restrict__ vis,
                               const float4* __restrict__ emb_len,
                               const float4* __restrict__ emb_id,
                               const float4* __restrict__ emb_lng,
                               const float4* __restrict__ emb_lat,
                               float4* __restrict__ x, int n) {
    int idx = blockIdx.x * blockDim.x + threadIdx.x;
    if (idx >= n * 32) return;
    int node = idx >> 5;
    int q = idx & 31;
    float4 v;
    if (q < 16) {
        int which = q >> 2;  // 0:id 1:len 2:lng 3:lat
        int sub = q & 3;
        int a;
        const float4* tab;
        if (which == 0)      { a = node_attr[node * 4 + 1]; tab = emb_id; }
        else if (which == 1) { a = node_attr[node * 4 + 0]; tab = emb_len; }
        else if (which == 2) { a = node_attr[node * 4 + 2]; tab = emb_lng; }
        else                 { a = node_attr[node * 4 + 3]; tab = emb_lat; }
        v = tab[a * 4 + sub];
    } else {
        v = vis[node * 16 + (q - 16)];
    }
    x[idx] = v;
}

// ---------------- gather propagation: out[n] = sum_{e: dst=n} w_e * t[src_e] ----------------
__global__ void prop_gather(const float* __restrict__ t,
                            const int* __restrict__ rs, const int* __restrict__ cnt,
                            const int* __restrict__ esrc, const float* __restrict__ ew,
                            float* __restrict__ out, int n) {
    int warp = (blockIdx.x * blockDim.x + threadIdx.x) >> 5;
    int lane = threadIdx.x & 31;
    if (warp >= n) return;
    int start = rs[warp];
    int end = start + cnt[warp];
    float ax = 0.f, ay = 0.f, az = 0.f, aw = 0.f;
    int j = start;
    for (; j + 4 <= end; j += 4) {
        int s0 = esrc[j], s1 = esrc[j + 1], s2 = esrc[j + 2], s3 = esrc[j + 3];
        float w0 = ew[j], w1 = ew[j + 1], w2 = ew[j + 2], w3 = ew[j + 3];
        float4 v0 = *(const float4*)(t + (size_t)s0 * 128 + lane * 4);
        float4 v1 = *(const float4*)(t + (size_t)s1 * 128 + lane * 4);
        float4 v2 = *(const float4*)(t + (size_t)s2 * 128 + lane * 4);
        float4 v3 = *(const float4*)(t + (size_t)s3 * 128 + lane * 4);
        ax += w0 * v0.x; ay += w0 * v0.y; az += w0 * v0.z; aw += w0 * v0.w;
        ax += w1 * v1.x; ay += w1 * v1.y; az += w1 * v1.z; aw += w1 * v1.w;
        ax += w2 * v2.x; ay += w2 * v2.y; az += w2 * v2.z; aw += w2 * v2.w;
        ax += w3 * v3.x; ay += w3 * v3.y; az += w3 * v3.z; aw += w3 * v3.w;
    }
    for (; j < end; j++) {
        int s = esrc[j];
        float w = ew[j];
        float4 v = *(const float4*)(t + (size_t)s * 128 + lane * 4);
        ax += w * v.x; ay += w * v.y; az += w * v.z; aw += w * v.w;
    }
    float4 r = make_float4(ax, ay, az, aw);
    *(float4*)(out + (size_t)warp * 128 + lane * 4) = r;
}

// ---------------- 3xTF32 tensor-core GEMM ----------------
__device__ __forceinline__ unsigned f2tf32(float f) {
    unsigned r;
    asm("cvt.rna.tf32.f32 %0, %1;" : "=r"(r) : "f"(f));
    return r;
}

__device__ __forceinline__ void mma_tf32(float& d0, float& d1, float& d2, float& d3,
                                         unsigned a0, unsigned a1, unsigned a2, unsigned a3,
                                         unsigned b0, unsigned b1) {
    asm volatile(
        "mma.sync.aligned.m16n8k8.row.col.f32.tf32.tf32.f32 "
        "{%0,%1,%2,%3}, {%4,%5,%6,%7}, {%8,%9}, {%0,%1,%2,%3};"
        : "+f"(d0), "+f"(d1), "+f"(d2), "+f"(d3)
        : "r"(a0), "r"(a1), "r"(a2), "r"(a3), "r"(b0), "r"(b1));
}

// C[M,NOUT] = A[M,KTOT] @ W[KTOT,NOUT] + bias; EPI: 0=none 1=relu 2=elu
// CHEB: A cols 0..127 = A0, 128..255 = A1, 256..383 = 2*A2 - A0
template<int KTOT, int NOUT, int EPI, bool CHEB>
__global__ void __launch_bounds__(256)
gemm_tf32(const float* __restrict__ A0, const float* __restrict__ A1,
          const float* __restrict__ A2, const float* __restrict__ W,
          const float* __restrict__ bias, float* __restrict__ C, int M) {
    constexpr int BM = 128, BK = 16, BN = NOUT;
    constexpr int WARP_N = BN / 2;
    constexpr int NT = WARP_N / 8;

    __shared__ unsigned Ah[BK][BM + 8], Al[BK][BM + 8];
    __shared__ unsigned Bh[BK][BN + 8], Bl[BK][BN + 8];

    const int tid = threadIdx.x;
    const int w = tid >> 5, lane = tid & 31;
    const int wm = w & 3, wn = w >> 2;
    const int gid = lane >> 2, tig = lane & 3;
    const int row0 = blockIdx.x * BM;

    float acc[2][NT][4];
#pragma unroll
    for (int mt = 0; mt < 2; mt++)
#pragma unroll
        for (int nt = 0; nt < NT; nt++)
#pragma unroll
            for (int q = 0; q < 4; q++) acc[mt][nt][q] = 0.f;

    for (int k0 = 0; k0 < KTOT; k0 += BK) {
        // ---- stage A: threads span M (conflict-free STS) ----
#pragma unroll
        for (int it = 0; it < 2; it++) {
            int i = tid + it * 256;        // 0..511
            int r = i & 127;               // m within tile
            int c4 = i >> 7;               // which float4 along k (0..3)
            int grow = row0 + r;
            int gk = k0 + c4 * 4;
            float4 v = make_float4(0.f, 0.f, 0.f, 0.f);
            if (grow < M) {
                if (CHEB) {
                    if (gk < 128) {
                        v = *(const float4*)(A0 + (size_t)grow * 128 + gk);
                    } else if (gk < 256) {
                        v = *(const float4*)(A1 + (size_t)grow * 128 + (gk - 128));
                    } else {
                        float4 p = *(const float4*)(A2 + (size_t)grow * 128 + (gk - 256));
                        float4 t = *(const float4*)(A0 + (size_t)grow * 128 + (gk - 256));
                        v = make_float4(2.f * p.x - t.x, 2.f * p.y - t.y,
                                        2.f * p.z - t.z, 2.f * p.w - t.w);
                    }
                } else {
                    v = *(const float4*)(A0 + (size_t)grow * KTOT + gk);
                }
            }
            float fv[4] = {v.x, v.y, v.z, v.w};
#pragma unroll
            for (int j = 0; j < 4; j++) {
                unsigned hi = f2tf32(fv[j]);
                unsigned lo = f2tf32(fv[j] - __uint_as_float(hi));
                Ah[c4 * 4 + j][r] = hi;
                Al[c4 * 4 + j][r] = lo;
            }
        }
        // ---- stage B (W) ----
#pragma unroll
        for (int it = 0; it < BN / 64; it++) {
            int i = tid + it * 256;
            int kk = i / (BN / 4);
            int c = (i % (BN / 4)) * 4;
            float4 v = *(const float4*)(W + (size_t)(k0 + kk) * BN + c);
            float fv[4] = {v.x, v.y, v.z, v.w};
            unsigned h4[4], l4[4];
#pragma unroll
            for (int j = 0; j < 4; j++) {
                h4[j] = f2tf32(fv[j]);
                l4[j] = f2tf32(fv[j] - __uint_as_float(h4[j]));
            }
            *(uint4*)&Bh[kk][c] = make_uint4(h4[0], h4[1], h4[2], h4[3]);
            *(uint4*)&Bl[kk][c] = make_uint4(l4[0], l4[1], l4[2], l4[3]);
        }
        __syncthreads();

#pragma unroll
        for (int ks = 0; ks < 2; ks++) {
            const int kr = ks * 8 + tig;
            unsigned ah[2][4], al[2][4];
#pragma unroll
            for (int mt = 0; mt < 2; mt++) {
                int m0 = wm * 32 + mt * 16 + gid;
                ah[mt][0] = Ah[kr][m0];     ah[mt][1] = Ah[kr][m0 + 8];
                ah[mt][2] = Ah[kr + 4][m0]; ah[mt][3] = Ah[kr + 4][m0 + 8];
                al[mt][0] = Al[kr][m0];     al[mt][1] = Al[kr][m0 + 8];
                al[mt][2] = Al[kr + 4][m0]; al[mt][3] = Al[kr + 4][m0 + 8];
            }
            unsigned bh[NT][2], bl[NT][2];
#pragma unroll
            for (int nt = 0; nt < NT; nt++) {
                int n0 = wn * WARP_N + nt * 8 + gid;
                bh[nt][0] = Bh[kr][n0]; bh[nt][1] = Bh[kr + 4][n0];
                bl[nt][0] = Bl[kr][n0]; bl[nt][1] = Bl[kr + 4][n0];
            }
#pragma unroll
            for (int mt = 0; mt < 2; mt++)
#pragma unroll
                for (int nt = 0; nt < NT; nt++) {
                    float* d = acc[mt][nt];
                    mma_tf32(d[0], d[1], d[2], d[3],
                             ah[mt][0], ah[mt][1], ah[mt][2], ah[mt][3],
                             bh[nt][0], bh[nt][1]);
                    mma_tf32(d[0], d[1], d[2], d[3],
                             ah[mt][0], ah[mt][1], ah[mt][2], ah[mt][3],
                             bl[nt][0], bl[nt][1]);
                    mma_tf32(d[0], d[1], d[2], d[3],
                             al[mt][0], al[mt][1], al[mt][2], al[mt][3],
                             bh[nt][0], bh[nt][1]);
                }
        }
        __syncthreads();
    }

    // ---- epilogue ----
#pragma unroll
    for (int mt = 0; mt < 2; mt++) {
#pragma unroll
        for (int nt = 0; nt < NT; nt++) {
            int c0 = wn * WARP_N + nt * 8 + tig * 2;
            float bv0 = bias[c0], bv1 = bias[c0 + 1];
#pragma unroll
            for (int half = 0; half < 2; half++) {
                int r = row0 + wm * 32 + mt * 16 + gid + half * 8;
                if (r >= M) continue;
                float v0 = acc[mt][nt][half * 2 + 0] + bv0;
                float v1 = acc[mt][nt][half * 2 + 1] + bv1;
                if (EPI == 1) { v0 = fmaxf(v0, 0.f); v1 = fmaxf(v1, 0.f); }
                else if (EPI == 2) {
                    v0 = (v0 > 0.f) ? v0 : expm1f(v0);
                    v1 = (v1 > 0.f) ? v1 : expm1f(v1);
                }
                *(float2*)(C + (size_t)r * NOUT + c0) = make_float2(v0, v1);
            }
        }
    }
}

// ---------------- launch ----------------
extern "C" void kernel_launch(void* const* d_in, const int* in_sizes, int n_in,
                              void* d_out, int out_size) {
    const int* edge_index = (const int*)d_in[0];
    const int* node_attr = (const int*)d_in[1];
    const float* vis     = (const float*)d_in[2];
    const float* emb_len = (const float*)d_in[3];
    const float* emb_id  = (const float*)d_in[4];
    const float* emb_lng = (const float*)d_in[5];
    const float* emb_lat = (const float*)d_in[6];
    const float* W0  = (const float*)d_in[7];
    const float* b0  = (const float*)d_in[8];
    const float* W1  = (const float*)d_in[9];
    const float* b1  = (const float*)d_in[10];
    const float* P1  = (const float*)d_in[11];
    const float* pb1 = (const float*)d_in[12];
    const float* P2  = (const float*)d_in[13];
    const float* pb2 = (const float*)d_in[14];

    const int E = in_sizes[0] / 2;
    const int N = in_sizes[1] / 4;
    const int* src = edge_index;
    const int* dst = edge_index + E;

    float *x, *t1, *p, *h1, *tmp, *dinv, *ew;
    int *deg, *cnt, *rs, *rf, *bsum, *boff, *esrc;
    cudaGetSymbolAddress((void**)&x,    g_x);
    cudaGetSymbolAddress((void**)&t1,   g_t1);
    cudaGetSymbolAddress((void**)&p,    g_p);
    cudaGetSymbolAddress((void**)&h1,   g_h1);
    cudaGetSymbolAddress((void**)&tmp,  g_tmp);
    cudaGetSymbolAddress((void**)&dinv, g_dinv);
    cudaGetSymbolAddress((void**)&deg,  g_deg);
    cudaGetSymbolAddress((void**)&cnt,  g_cnt);
    cudaGetSymbolAddress((void**)&rs,   g_rs);
    cudaGetSymbolAddress((void**)&rf,   g_rf);
    cudaGetSymbolAddress((void**)&bsum, g_bsum);
    cudaGetSymbolAddress((void**)&boff, g_boff);
    cudaGetSymbolAddress((void**)&esrc, g_esrc);
    cudaGetSymbolAddress((void**)&ew,   g_ew);

    float* hout = (float*)d_out;
    float* zout = hout + (size_t)N * 128;

    const int nb = (N + 255) / 256;
    const int eb = (E + 255) / 256;
    const int gemm_blocks = (N + 127) / 128;
    const int prop_blocks = (N * 32 + 255) / 256;

    // CSR build + dinv
    zero_int_kernel<<<nb, 256>>>(deg, cnt, N);
    count_kernel<<<eb, 256>>>(src, dst, deg, cnt, E);
    dinv_kernel<<<nb, 256>>>(deg, dinv, N);
    scan_block_sum<<<nb, 256>>>(cnt, bsum, N);
    scan_top<<<1, 256>>>(bsum, boff, nb);
    scan_final<<<nb, 256>>>(cnt, boff, rs, rf, N);
    fill_kernel<<<eb, 256>>>(src, dst, dinv, rf, esrc, ew, E);

    // feature assembly
    build_x_kernel<<<(N * 32 + 255) / 256, 256>>>(node_attr, (const float4*)vis,
        (const float4*)emb_len, (const float4*)emb_id,
        (const float4*)emb_lng, (const float4*)emb_lat, (float4*)x, N);

    // ---- conv1 ----
    prop_gather<<<prop_blocks, 256>>>(x, rs, cnt, esrc, ew, t1, N);
    prop_gather<<<prop_blocks, 256>>>(t1, rs, cnt, esrc, ew, p, N);
    gemm_tf32<384, 128, 1, true><<<gemm_blocks, 256>>>(x, t1, p, W0, b0, h1, N);

    // ---- conv2 ----
    prop_gather<<<prop_blocks, 256>>>(h1, rs, cnt, esrc, ew, t1, N);
    prop_gather<<<prop_blocks, 256>>>(t1, rs, cnt, esrc, ew, p, N);
    gemm_tf32<384, 128, 1, true><<<gemm_blocks, 256>>>(h1, t1, p, W1, b1, hout, N);

    // ---- projection head ----
    gemm_tf32<128, 128, 2, false><<<gemm_blocks, 256>>>(hout, nullptr, nullptr, P1, pb1, tmp, N);
    gemm_tf32<128, 64, 0, false><<<gemm_blocks, 256>>>(tmp, nullptr, nullptr, P2, pb2, zout, N);
}